// round 8
// baseline (speedup 1.0000x reference)
#include <cuda_runtime.h>

typedef unsigned long long ULL;

// gx scratch: [B=256][T=512][G=512] fp32 = 256 MiB (module BSS; no runtime alloc)
__device__ __align__(16) float g_gx[256u * 512u * 512u];

__device__ __forceinline__ void ffma2(ULL& d, ULL a, ULL b) {
    asm("fma.rn.f32x2 %0, %1, %2, %0;" : "+l"(d) : "l"(a), "l"(b));
}
__device__ __forceinline__ ULL dup2(float x) {
    ULL r; asm("mov.b64 %0, {%1, %1};" : "=l"(r) : "f"(x)); return r;
}
__device__ __forceinline__ float2 unpack2(ULL v) {
    float2 f; asm("mov.b64 {%0, %1}, %2;" : "=f"(f.x), "=f"(f.y) : "l"(v)); return f;
}

__device__ __forceinline__ float sigmoidf_(float x) {
    return 1.0f / (1.0f + __expf(-x));
}
__device__ __forceinline__ float tanhf_(float x) {
    float ax = fabsf(x);
    float e = __expf(-2.0f * ax);          // in (0,1], no overflow
    float t = (1.0f - e) / (1.0f + e);
    return copysignf(t, x);
}

// ---------------------------------------------------------------------------
// Kernel 1 (unchanged, known-good): gx = X @ W_ih^T + (b_ih + b_hh)
// M=131072, N=512, K=300. 128x128x8 tiles, f32x2-packed accumulators,
// double-buffered smem, whole-block length skipping.
// ---------------------------------------------------------------------------
__device__ __forceinline__ void gemm_compute_tile(
    const float* __restrict__ ab, const float* __restrict__ bb,
    int m0, int n0, ULL (&acc)[8][4])
{
#pragma unroll
    for (int kk = 0; kk < 8; ++kk) {
        float4 a0 = *(const float4*)(ab + kk * 132 + m0);
        float4 a1 = *(const float4*)(ab + kk * 132 + m0 + 4);
        ulonglong2 bb0 = *(const ulonglong2*)(bb + kk * 132 + n0);
        ulonglong2 bb1 = *(const ulonglong2*)(bb + kk * 132 + n0 + 4);
        float av[8] = {a0.x, a0.y, a0.z, a0.w, a1.x, a1.y, a1.z, a1.w};
#pragma unroll
        for (int i = 0; i < 8; ++i) {
            ULL ad = dup2(av[i]);
            ffma2(acc[i][0], ad, bb0.x);
            ffma2(acc[i][1], ad, bb0.y);
            ffma2(acc[i][2], ad, bb1.x);
            ffma2(acc[i][3], ad, bb1.y);
        }
    }
}

__global__ __launch_bounds__(256, 2)
void k_gemm_gx(const float* __restrict__ X, const float* __restrict__ W,
               const float* __restrict__ b_ih, const float* __restrict__ b_hh,
               const int* __restrict__ lengths)
{
    const int bm = blockIdx.x;
    const int bn = blockIdx.y;
    const int bseq = bm >> 2;
    const int tblk = bm & 3;
    if (tblk * 128 >= lengths[bseq]) return;

    __shared__ __align__(16) float As[2 * 8 * 132];
    __shared__ __align__(16) float Bs[2 * 8 * 132];

    const int tid = threadIdx.x;
    const int ty = tid >> 4, tx = tid & 15;
    const int m0 = ty * 8, n0 = tx * 8;
    const int lrow = tid >> 1;
    const int kb = (tid & 1) * 4;
    const int bm0 = bm * 128;
    const int bn0 = bn * 128;

    const float* Arow = X + (size_t)(bm0 + lrow) * 300 + kb;
    const float* Brow = W + (size_t)(bn0 + lrow) * 300 + kb;

    ULL acc[8][4];
#pragma unroll
    for (int i = 0; i < 8; ++i)
#pragma unroll
        for (int j = 0; j < 4; ++j) acc[i][j] = 0ull;

    {
        float4 fa = *(const float4*)(Arow);
        float4 fb = *(const float4*)(Brow);
        float* a = As; float* b = Bs;
        a[(kb + 0) * 132 + lrow] = fa.x; a[(kb + 1) * 132 + lrow] = fa.y;
        a[(kb + 2) * 132 + lrow] = fa.z; a[(kb + 3) * 132 + lrow] = fa.w;
        b[(kb + 0) * 132 + lrow] = fb.x; b[(kb + 1) * 132 + lrow] = fb.y;
        b[(kb + 2) * 132 + lrow] = fb.z; b[(kb + 3) * 132 + lrow] = fb.w;
    }
    __syncthreads();

#pragma unroll 1
    for (int it = 1; it < 38; ++it) {
        int k = it * 8 + kb;
        float4 na, nb;
        if (k < 300) {
            na = *(const float4*)(Arow + it * 8);
            nb = *(const float4*)(Brow + it * 8);
        } else {
            na = make_float4(0.f, 0.f, 0.f, 0.f);
            nb = na;
        }
        gemm_compute_tile(As + ((it - 1) & 1) * 1056,
                          Bs + ((it - 1) & 1) * 1056, m0, n0, acc);
        {
            float* a = As + (it & 1) * 1056;
            float* b = Bs + (it & 1) * 1056;
            a[(kb + 0) * 132 + lrow] = na.x; a[(kb + 1) * 132 + lrow] = na.y;
            a[(kb + 2) * 132 + lrow] = na.z; a[(kb + 3) * 132 + lrow] = na.w;
            b[(kb + 0) * 132 + lrow] = nb.x; b[(kb + 1) * 132 + lrow] = nb.y;
            b[(kb + 2) * 132 + lrow] = nb.z; b[(kb + 3) * 132 + lrow] = nb.w;
        }
        __syncthreads();
    }
    gemm_compute_tile(As + 1056, Bs + 1056, m0, n0, acc);

    float bias[8];
#pragma unroll
    for (int j = 0; j < 8; ++j)
        bias[j] = b_ih[bn0 + n0 + j] + b_hh[bn0 + n0 + j];

#pragma unroll
    for (int i = 0; i < 8; ++i) {
        float2 v0 = unpack2(acc[i][0]);
        float2 v1 = unpack2(acc[i][1]);
        float2 v2 = unpack2(acc[i][2]);
        float2 v3 = unpack2(acc[i][3]);
        float4 o0 = make_float4(v0.x + bias[0], v0.y + bias[1],
                                v1.x + bias[2], v1.y + bias[3]);
        float4 o1 = make_float4(v2.x + bias[4], v2.y + bias[5],
                                v3.x + bias[6], v3.y + bias[7]);
        size_t row = (size_t)(bm0 + m0 + i) * 512 + bn0 + n0;
        *(float4*)&g_gx[row]     = o0;
        *(float4*)&g_gx[row + 4] = o1;
    }
}

// ---------------------------------------------------------------------------
// Kernel 2 v2: LSTM recurrence + final FC.
// 128 CTAs x 512 threads (16 warps -> 2x latency hiding vs v1).
// CTA owns batch rows b0, b0+1. Thread tid owns ONE gate row r = tid of W_hh:
// first 64 weights in registers (16 ull2), last 64 in smem (128 KB/CTA,
// no duplication). Each thread computes gate[r] for BOTH batch rows
// (h vectors are smem broadcasts). Gates exchanged via smem; update phase
// (tid < 256) owns c-state and applies the length mask.
// ---------------------------------------------------------------------------
#define K2_SMEM_BYTES (16 * 512 * 16 + 2 * 128 * 4 + 2 * 512 * 4)

__global__ __launch_bounds__(512, 1)
void k_lstm(const float* __restrict__ Whh, const float* __restrict__ fcw,
            const float* __restrict__ fcb, const int* __restrict__ lengths,
            float* __restrict__ out)
{
    extern __shared__ __align__(16) float sm[];
    ulonglong2* sw = (ulonglong2*)sm;           // [16][512] ull2 = 128 KB
    float* hbuf = sm + 32768;                   // [2][128]
    float* gsm  = hbuf + 256;                   // [2][512]

    const int tid = threadIdx.x;                // 0..511 = gate row r
    const int b0 = blockIdx.x * 2;

    // load weight row tid: 32 ull2; j 0..15 -> regs (k 0..63), 16..31 -> smem
    ulonglong2 wr[16];
    {
        const ulonglong2* w = (const ulonglong2*)(Whh + (size_t)tid * 128);
#pragma unroll
        for (int j = 0; j < 16; ++j) wr[j] = w[j];
#pragma unroll
        for (int j = 0; j < 16; ++j) sw[j * 512 + tid] = w[16 + j];
    }
    if (tid < 256) { hbuf[tid] = 0.0f; }        // covers [2][128]

    const int ub = tid >> 7;                    // (update phase) batch row
    const int uj = tid & 127;                   // (update phase) h element
    const int len0 = lengths[b0];
    const int len1 = lengths[b0 + 1];
    const int mylen = (ub == 0) ? len0 : len1;  // only used when tid < 256
    const int tmax = (len0 > len1) ? len0 : len1;
    float creg = 0.0f;

    const float* gxp0 = g_gx + (size_t)b0 * 512 * 512;
    const float* gxp1 = g_gx + (size_t)(b0 + 1) * 512 * 512;
    __syncthreads();

    for (int t = 0; t < tmax; ++t) {
        // prefetch gx early; consumed after the dot phase
        const float gx0 = gxp0[(size_t)t * 512 + tid];   // (b0, row tid)
        const float gx1 = gxp1[(size_t)t * 512 + tid];   // (b1, row tid)

        ULL a0 = 0ull, a1 = 0ull;
        const ulonglong2* h0 = (const ulonglong2*)hbuf;         // batch 0 h
        const ulonglong2* h1 = (const ulonglong2*)(hbuf + 128); // batch 1 h

#pragma unroll
        for (int j = 0; j < 16; ++j) {           // register weight half, k 0..63
            ulonglong2 hv0 = h0[j], hv1 = h1[j];
            ulonglong2 w = wr[j];
            ffma2(a0, w.x, hv0.x); ffma2(a0, w.y, hv0.y);
            ffma2(a1, w.x, hv1.x); ffma2(a1, w.y, hv1.y);
        }
#pragma unroll
        for (int j = 0; j < 16; ++j) {           // smem weight half, k 64..127
            ulonglong2 hv0 = h0[16 + j], hv1 = h1[16 + j];
            ulonglong2 w = sw[j * 512 + tid];
            ffma2(a0, w.x, hv0.x); ffma2(a0, w.y, hv0.y);
            ffma2(a1, w.x, hv1.x); ffma2(a1, w.y, hv1.y);
        }

        float2 v;
        v = unpack2(a0); gsm[tid]       = v.x + v.y + gx0;
        v = unpack2(a1); gsm[512 + tid] = v.x + v.y + gx1;
        __syncthreads();

        // update phase: threads 0..255 cover 2 batches x 128 h-elements
        if (tid < 256) {
            const float gi = gsm[ub * 512 + uj];
            const float gf = gsm[ub * 512 + 128 + uj];
            const float gg = gsm[ub * 512 + 256 + uj];
            const float go = gsm[ub * 512 + 384 + uj];
            const float i_ = sigmoidf_(gi);
            const float f_ = sigmoidf_(gf);
            const float g_ = tanhf_(gg);
            const float o_ = sigmoidf_(go);
            const float cn = f_ * creg + i_ * g_;
            const float hn = o_ * tanhf_(cn);
            const bool valid = (t < mylen);
            const float hold = hbuf[ub * 128 + uj];
            creg = valid ? cn : creg;
            hbuf[ub * 128 + uj] = valid ? hn : hold;
        }
        __syncthreads();
    }

    // final FC: out[b][c] = h[b] . fc_w[c] + fc_b[c]
    if (tid < 12) {
        const int bb = tid / 6, c = tid % 6;
        const float* h = hbuf + bb * 128;
        const float* w = fcw + c * 128;
        float s = fcb[c];
#pragma unroll 8
        for (int k = 0; k < 128; ++k) s += h[k] * w[k];
        out[(b0 + bb) * 6 + c] = s;
    }
}

// ---------------------------------------------------------------------------
extern "C" void kernel_launch(void* const* d_in, const int* in_sizes, int n_in,
                              void* d_out, int out_size)
{
    (void)in_sizes; (void)n_in; (void)out_size;
    const float* x       = (const float*)d_in[0];   // [256][512][300]
    const float* W_ih    = (const float*)d_in[1];   // [512][300]
    const float* W_hh    = (const float*)d_in[2];   // [512][128]
    const float* b_ih    = (const float*)d_in[3];   // [512]
    const float* b_hh    = (const float*)d_in[4];   // [512]
    const float* fc_w    = (const float*)d_in[5];   // [6][128]
    const float* fc_b    = (const float*)d_in[6];   // [6]
    const int*   lengths = (const int*)d_in[7];     // [256]
    float* out = (float*)d_out;                     // [256][6]

    dim3 g1(1024, 4);
    k_gemm_gx<<<g1, 256>>>(x, W_ih, b_ih, b_hh, lengths);

    (void)cudaFuncSetAttribute(k_lstm,
                               cudaFuncAttributeMaxDynamicSharedMemorySize,
                               K2_SMEM_BYTES);
    k_lstm<<<128, 512, K2_SMEM_BYTES>>>(W_hh, fc_w, fc_b, lengths, out);
}

// round 9
// speedup vs baseline: 1.2506x; 1.2506x over previous
#include <cuda_runtime.h>

typedef unsigned long long ULL;

// gx scratch: [B=256][T=512][G=512] fp32 = 256 MiB (module BSS; no runtime alloc)
__device__ __align__(16) float g_gx[256u * 512u * 512u];
// LSTM state carried across chunk kernels
__device__ __align__(16) float g_h[256 * 128];
__device__ __align__(16) float g_c[256 * 128];

__device__ __forceinline__ void ffma2(ULL& d, ULL a, ULL b) {
    asm("fma.rn.f32x2 %0, %1, %2, %0;" : "+l"(d) : "l"(a), "l"(b));
}
__device__ __forceinline__ ULL dup2(float x) {
    ULL r; asm("mov.b64 %0, {%1, %1};" : "=l"(r) : "f"(x)); return r;
}
__device__ __forceinline__ float2 unpack2(ULL v) {
    float2 f; asm("mov.b64 {%0, %1}, %2;" : "=f"(f.x), "=f"(f.y) : "l"(v)); return f;
}

__device__ __forceinline__ float sigmoidf_(float x) {
    return 1.0f / (1.0f + __expf(-x));
}
__device__ __forceinline__ float tanhf_(float x) {
    float ax = fabsf(x);
    float e = __expf(-2.0f * ax);
    float t = (1.0f - e) / (1.0f + e);
    return copysignf(t, x);
}

// ---------------------------------------------------------------------------
// GEMM chunk: gx rows for t in [t0, t0+64) of every batch.
// BM=64 (one 64-step slice of one batch), BN=128, BK=8, 128 threads,
// 8x8 micro-tile, f32x2-packed accumulators, double-buffered smem.
// Skips batches with t0 >= length[b].
// ---------------------------------------------------------------------------
__device__ __forceinline__ void gemm_tile64(
    const float* __restrict__ ab, const float* __restrict__ bb,
    int m0, int n0, ULL (&acc)[8][4])
{
#pragma unroll
    for (int kk = 0; kk < 8; ++kk) {
        float4 a0 = *(const float4*)(ab + kk * 68 + m0);
        float4 a1 = *(const float4*)(ab + kk * 68 + m0 + 4);
        ulonglong2 bb0 = *(const ulonglong2*)(bb + kk * 132 + n0);
        ulonglong2 bb1 = *(const ulonglong2*)(bb + kk * 132 + n0 + 4);
        float av[8] = {a0.x, a0.y, a0.z, a0.w, a1.x, a1.y, a1.z, a1.w};
#pragma unroll
        for (int i = 0; i < 8; ++i) {
            ULL ad = dup2(av[i]);
            ffma2(acc[i][0], ad, bb0.x);
            ffma2(acc[i][1], ad, bb0.y);
            ffma2(acc[i][2], ad, bb1.x);
            ffma2(acc[i][3], ad, bb1.y);
        }
    }
}

__global__ __launch_bounds__(128, 4)
void k_gemm_gx64(const float* __restrict__ X, const float* __restrict__ W,
                 const float* __restrict__ b_ih, const float* __restrict__ b_hh,
                 const int* __restrict__ lengths, int t0)
{
    const int batch = blockIdx.x;         // 0..255
    const int bn = blockIdx.y;            // 0..3
    if (t0 >= lengths[batch]) return;

    __shared__ __align__(16) float As[2 * 8 * 68];
    __shared__ __align__(16) float Bs[2 * 8 * 132];

    const int tid = threadIdx.x;          // 0..127
    const int ty = tid >> 4, tx = tid & 15;
    const int m0 = ty * 8, n0 = tx * 8;
    const int rowA = tid >> 1;            // 0..63
    const int kbA = (tid & 1) * 4;        // 0 or 4
    const int bn0 = bn * 128;

    const size_t mbase = (size_t)batch * 512 + t0;
    const float* Arow = X + (mbase + rowA) * 300 + kbA;
    const float* Brow = W + (size_t)(bn0 + tid) * 300;

    ULL acc[8][4];
#pragma unroll
    for (int i = 0; i < 8; ++i)
#pragma unroll
        for (int j = 0; j < 4; ++j) acc[i][j] = 0ull;

    // prologue: k-tile 0 into buffer 0 (all in-bounds)
    {
        float4 fa = *(const float4*)(Arow);
        float4 fb0 = *(const float4*)(Brow);
        float4 fb1 = *(const float4*)(Brow + 4);
        float* a = As; float* b = Bs;
        a[(kbA + 0) * 68 + rowA] = fa.x; a[(kbA + 1) * 68 + rowA] = fa.y;
        a[(kbA + 2) * 68 + rowA] = fa.z; a[(kbA + 3) * 68 + rowA] = fa.w;
        b[0 * 132 + tid] = fb0.x; b[1 * 132 + tid] = fb0.y;
        b[2 * 132 + tid] = fb0.z; b[3 * 132 + tid] = fb0.w;
        b[4 * 132 + tid] = fb1.x; b[5 * 132 + tid] = fb1.y;
        b[6 * 132 + tid] = fb1.z; b[7 * 132 + tid] = fb1.w;
    }
    __syncthreads();

#pragma unroll 1
    for (int it = 1; it < 38; ++it) {     // 38 k-tiles cover K=300 (zero-padded)
        const int kA = it * 8 + kbA;
        float4 na = (kA < 300) ? *(const float4*)(Arow + it * 8)
                               : make_float4(0.f, 0.f, 0.f, 0.f);
        float4 nb0 = *(const float4*)(Brow + it * 8);          // it*8 <= 296
        float4 nb1 = (it * 8 + 4 < 300) ? *(const float4*)(Brow + it * 8 + 4)
                                        : make_float4(0.f, 0.f, 0.f, 0.f);

        gemm_tile64(As + ((it - 1) & 1) * 544,
                    Bs + ((it - 1) & 1) * 1056, m0, n0, acc);
        {
            float* a = As + (it & 1) * 544;
            float* b = Bs + (it & 1) * 1056;
            a[(kbA + 0) * 68 + rowA] = na.x; a[(kbA + 1) * 68 + rowA] = na.y;
            a[(kbA + 2) * 68 + rowA] = na.z; a[(kbA + 3) * 68 + rowA] = na.w;
            b[0 * 132 + tid] = nb0.x; b[1 * 132 + tid] = nb0.y;
            b[2 * 132 + tid] = nb0.z; b[3 * 132 + tid] = nb0.w;
            b[4 * 132 + tid] = nb1.x; b[5 * 132 + tid] = nb1.y;
            b[6 * 132 + tid] = nb1.z; b[7 * 132 + tid] = nb1.w;
        }
        __syncthreads();
    }
    gemm_tile64(As + 544, Bs + 1056, m0, n0, acc);  // buffer (37&1)=1

    float bias[8];
#pragma unroll
    for (int j = 0; j < 8; ++j)
        bias[j] = b_ih[bn0 + n0 + j] + b_hh[bn0 + n0 + j];

#pragma unroll
    for (int i = 0; i < 8; ++i) {
        float2 v0 = unpack2(acc[i][0]);
        float2 v1 = unpack2(acc[i][1]);
        float2 v2 = unpack2(acc[i][2]);
        float2 v3 = unpack2(acc[i][3]);
        float4 o0 = make_float4(v0.x + bias[0], v0.y + bias[1],
                                v1.x + bias[2], v1.y + bias[3]);
        float4 o1 = make_float4(v2.x + bias[4], v2.y + bias[5],
                                v3.x + bias[6], v3.y + bias[7]);
        size_t row = (mbase + m0 + i) * 512 + bn0 + n0;
        *(float4*)&g_gx[row]     = o0;
        *(float4*)&g_gx[row + 4] = o1;
    }
}

// ---------------------------------------------------------------------------
// LSTM chunk: steps t in [t0, min(t1, tmax)). v1 structure: 128 CTAs x 256
// threads, CTA owns batch rows b0,b0+1, thread owns gate rows tid & tid+256
// (half weights in 128 regs, half in 128 KB smem), f32x2 dot products.
// h/c state persisted in g_h/g_c between chunks.
// ---------------------------------------------------------------------------
#define K2_SMEM_BYTES (32 * 256 * 16 + 2 * 128 * 4 + 2 * 512 * 4)

__global__ __launch_bounds__(256, 1)
void k_lstm_chunk(const float* __restrict__ Whh, const int* __restrict__ lengths,
                  int t0, int t1)
{
    const int b0 = blockIdx.x * 2;
    const int len0 = lengths[b0];
    const int len1 = lengths[b0 + 1];
    const int tmax = (len0 > len1) ? len0 : len1;
    if (t0 >= tmax) return;                     // state already final
    const int tend = (t1 < tmax) ? t1 : tmax;

    extern __shared__ __align__(16) float sm[];
    ulonglong2* sw = (ulonglong2*)sm;           // [32][256] ull2 = 128 KB
    float* hbuf = sm + 32768;                   // [2][128]
    float* gsm  = hbuf + 256;                   // [2][512]

    const int tid = threadIdx.x;
    const int r0 = tid, r1 = tid + 256;

    // weights: per row 32 ull2; j 0..15 -> regs, 16..31 -> smem
    ulonglong2 wr0[16], wr1[16];
    {
        const ulonglong2* w0 = (const ulonglong2*)(Whh + (size_t)r0 * 128);
        const ulonglong2* w1 = (const ulonglong2*)(Whh + (size_t)r1 * 128);
#pragma unroll
        for (int j = 0; j < 16; ++j) { wr0[j] = w0[j]; wr1[j] = w1[j]; }
#pragma unroll
        for (int j = 0; j < 16; ++j) {
            sw[j * 256 + tid]        = w0[16 + j];
            sw[(16 + j) * 256 + tid] = w1[16 + j];
        }
    }

    const int ub = tid >> 7;
    const int uj = tid & 127;
    const int mylen = (ub == 0) ? len0 : len1;
    float creg;
    if (t0 == 0) { hbuf[tid] = 0.0f; creg = 0.0f; }
    else         { hbuf[tid] = g_h[b0 * 128 + tid]; creg = g_c[b0 * 128 + tid]; }

    const float* gxp0 = g_gx + (size_t)b0 * 512 * 512;
    const float* gxp1 = g_gx + (size_t)(b0 + 1) * 512 * 512;
    __syncthreads();

    for (int t = t0; t < tend; ++t) {
        const float gx00 = gxp0[(size_t)t * 512 + r0];
        const float gx01 = gxp0[(size_t)t * 512 + r1];
        const float gx10 = gxp1[(size_t)t * 512 + r0];
        const float gx11 = gxp1[(size_t)t * 512 + r1];

        ULL a00 = 0ull, a01 = 0ull, a10 = 0ull, a11 = 0ull;
        const ulonglong2* h0 = (const ulonglong2*)hbuf;
        const ulonglong2* h1 = (const ulonglong2*)(hbuf + 128);

#pragma unroll
        for (int j = 0; j < 16; ++j) {
            ulonglong2 hv0 = h0[j], hv1 = h1[j];
            ulonglong2 w0 = wr0[j], w1 = wr1[j];
            ffma2(a00, w0.x, hv0.x); ffma2(a00, w0.y, hv0.y);
            ffma2(a01, w0.x, hv1.x); ffma2(a01, w0.y, hv1.y);
            ffma2(a10, w1.x, hv0.x); ffma2(a10, w1.y, hv0.y);
            ffma2(a11, w1.x, hv1.x); ffma2(a11, w1.y, hv1.y);
        }
#pragma unroll
        for (int j = 0; j < 16; ++j) {
            ulonglong2 hv0 = h0[16 + j], hv1 = h1[16 + j];
            ulonglong2 w0 = sw[j * 256 + tid];
            ulonglong2 w1 = sw[(16 + j) * 256 + tid];
            ffma2(a00, w0.x, hv0.x); ffma2(a00, w0.y, hv0.y);
            ffma2(a01, w0.x, hv1.x); ffma2(a01, w0.y, hv1.y);
            ffma2(a10, w1.x, hv0.x); ffma2(a10, w1.y, hv0.y);
            ffma2(a11, w1.x, hv1.x); ffma2(a11, w1.y, hv1.y);
        }

        float2 v;
        v = unpack2(a00); gsm[r0]       = v.x + v.y + gx00;
        v = unpack2(a10); gsm[r1]       = v.x + v.y + gx01;
        v = unpack2(a01); gsm[512 + r0] = v.x + v.y + gx10;
        v = unpack2(a11); gsm[512 + r1] = v.x + v.y + gx11;
        __syncthreads();

        {
            const float gi = gsm[ub * 512 + uj];
            const float gf = gsm[ub * 512 + 128 + uj];
            const float gg = gsm[ub * 512 + 256 + uj];
            const float go = gsm[ub * 512 + 384 + uj];
            const float i_ = sigmoidf_(gi);
            const float f_ = sigmoidf_(gf);
            const float g_ = tanhf_(gg);
            const float o_ = sigmoidf_(go);
            const float cn = f_ * creg + i_ * g_;
            const float hn = o_ * tanhf_(cn);
            const bool valid = (t < mylen);
            const float hold = hbuf[ub * 128 + uj];
            creg = valid ? cn : creg;
            hbuf[ub * 128 + uj] = valid ? hn : hold;
        }
        __syncthreads();
    }

    // persist state for the next chunk / FC
    g_h[b0 * 128 + tid] = hbuf[tid];
    g_c[b0 * 128 + tid] = creg;
}

// ---------------------------------------------------------------------------
// Final FC: out[b][c] = h[b] . fc_w[c] + fc_b[c]. One warp per batch.
// ---------------------------------------------------------------------------
__global__ void k_fc(const float* __restrict__ fcw, const float* __restrict__ fcb,
                     float* __restrict__ out)
{
    const int b = blockIdx.x;
    const int lane = threadIdx.x;       // 0..31
    const float* h = g_h + b * 128;
    const float h0 = h[lane], h1 = h[lane + 32], h2 = h[lane + 64], h3 = h[lane + 96];
#pragma unroll
    for (int c = 0; c < 6; ++c) {
        const float* w = fcw + c * 128;
        float s = h0 * w[lane] + h1 * w[lane + 32] + h2 * w[lane + 64] + h3 * w[lane + 96];
#pragma unroll
        for (int off = 16; off > 0; off >>= 1)
            s += __shfl_xor_sync(0xFFFFFFFFu, s, off);
        if (lane == 0) out[b * 6 + c] = s + fcb[c];
    }
}

// ---------------------------------------------------------------------------
#define N_CHUNKS 8
#define CHUNK_T 64

extern "C" void kernel_launch(void* const* d_in, const int* in_sizes, int n_in,
                              void* d_out, int out_size)
{
    (void)in_sizes; (void)n_in; (void)out_size;
    const float* x       = (const float*)d_in[0];   // [256][512][300]
    const float* W_ih    = (const float*)d_in[1];   // [512][300]
    const float* W_hh    = (const float*)d_in[2];   // [512][128]
    const float* b_ih    = (const float*)d_in[3];   // [512]
    const float* b_hh    = (const float*)d_in[4];   // [512]
    const float* fc_w    = (const float*)d_in[5];   // [6][128]
    const float* fc_b    = (const float*)d_in[6];   // [6]
    const int*   lengths = (const int*)d_in[7];     // [256]
    float* out = (float*)d_out;                     // [256][6]

    // One-time handle creation (first call is the uncaptured correctness run).
    static cudaStream_t s_g = 0;
    static cudaEvent_t ev_fork = 0;
    static cudaEvent_t ev_g[N_CHUNKS];
    static bool inited = false;
    if (!inited) {
        cudaStreamCreateWithFlags(&s_g, cudaStreamNonBlocking);
        cudaEventCreateWithFlags(&ev_fork, cudaEventDisableTiming);
        for (int c = 0; c < N_CHUNKS; ++c)
            cudaEventCreateWithFlags(&ev_g[c], cudaEventDisableTiming);
        (void)cudaFuncSetAttribute(k_lstm_chunk,
                                   cudaFuncAttributeMaxDynamicSharedMemorySize,
                                   K2_SMEM_BYTES);
        inited = true;
    }

    // Fork: side stream depends on main stream, runs all GEMM chunks.
    cudaEventRecord(ev_fork, 0);
    cudaStreamWaitEvent(s_g, ev_fork, 0);
    for (int c = 0; c < N_CHUNKS; ++c) {
        k_gemm_gx64<<<dim3(256, 4), 128, 0, s_g>>>(x, W_ih, b_ih, b_hh,
                                                   lengths, c * CHUNK_T);
        cudaEventRecord(ev_g[c], s_g);
    }

    // Main stream: LSTM chunk c waits only on GEMM chunk c (join via events).
    for (int c = 0; c < N_CHUNKS; ++c) {
        cudaStreamWaitEvent(0, ev_g[c], 0);
        k_lstm_chunk<<<128, 256, K2_SMEM_BYTES>>>(W_hh, lengths,
                                                  c * CHUNK_T, (c + 1) * CHUNK_T);
    }

    k_fc<<<256, 32>>>(fc_w, fc_b, out);
}